// round 7
// baseline (speedup 1.0000x reference)
#include <cuda_runtime.h>

#define NN 100000
#define DD 64
#define EE 1600000

// Scratch (no allocations allowed): AB = [A | B+b_msg] per node, message accum, counts.
__device__ __align__(16) float g_AB[NN * 128];
__device__ __align__(16) float g_msg[NN * DD];
__device__ float g_cnt[NN];

// ---------------------------------------------------------------------------
// Kernel 1: AB[n, 0:64]  = X[n] @ Wm_s^T
//           AB[n,64:128] = X[n] @ Wm_t^T + b_msg
// Also zeroes g_msg / g_cnt (grid-stride).
// 256 threads/block, 8 nodes/block (32 threads per node), W_msg in shared
// with stride-129 padding for conflict-free row reads.
// ---------------------------------------------------------------------------
__global__ void precompute_kernel(const float* __restrict__ x,
                                  const float* __restrict__ W_msg,
                                  const float* __restrict__ b_msg) {
    __shared__ float Ws[64 * 129];
    __shared__ float xs[8][64];
    const int tid = threadIdx.x;

    // Load W_msg (64 x 128) into padded shared.
    for (int i = tid; i < 64 * 128; i += 256) {
        Ws[(i >> 7) * 129 + (i & 127)] = W_msg[i];
    }

    // Zero scratch.
    const int gtid = blockIdx.x * 256 + tid;
    const int nth = gridDim.x * 256;
    for (int i = gtid; i < NN * DD; i += nth) g_msg[i] = 0.0f;
    for (int i = gtid; i < NN; i += nth) g_cnt[i] = 0.0f;

    const int group = tid >> 5;
    const int lane = tid & 31;
    const int node = blockIdx.x * 8 + group;

    xs[group][lane]      = x[node * 64 + lane];
    xs[group][lane + 32] = x[node * 64 + lane + 32];
    __syncthreads();

    #pragma unroll
    for (int t = 0; t < 4; ++t) {
        const int j2 = lane + t * 32;                 // 0..127
        const int row = (j2 < 64) ? j2 : (j2 - 64);
        const int coff = (j2 < 64) ? 0 : 64;
        float acc = (j2 < 64) ? 0.0f : __ldg(&b_msg[j2 - 64]);
        const float* wr = &Ws[row * 129 + coff];
        #pragma unroll
        for (int k = 0; k < 64; ++k) acc += xs[group][k] * wr[k];
        g_AB[node * 128 + j2] = acc;
    }
}

// ---------------------------------------------------------------------------
// Kernel 2: per edge e=(s,t): m = relu(A[s] + B[t]); red.add.v4 into g_msg[t];
// one count-red per edge. 16 threads per edge (one float4 each).
// edge_index arrives as int32 (harness downcasts the int64 reference input).
// ---------------------------------------------------------------------------
__global__ void edge_kernel(const int* __restrict__ ei) {
    const int gtid = blockIdx.x * 256 + threadIdx.x;
    const int e = gtid >> 4;
    if (e >= EE) return;
    const int q = gtid & 15;

    const int src = __ldg(&ei[2 * e]);
    const int tgt = __ldg(&ei[2 * e + 1]);

    const float4 a = *(const float4*)&g_AB[src * 128 + q * 4];
    const float4 b = *(const float4*)&g_AB[tgt * 128 + 64 + q * 4];
    float4 v;
    v.x = fmaxf(a.x + b.x, 0.0f);
    v.y = fmaxf(a.y + b.y, 0.0f);
    v.z = fmaxf(a.z + b.z, 0.0f);
    v.w = fmaxf(a.w + b.w, 0.0f);

    float* dst = &g_msg[tgt * 64 + q * 4];
    size_t gaddr = __cvta_generic_to_global(dst);
    asm volatile("red.global.add.v4.f32 [%0], {%1, %2, %3, %4};"
                 :: "l"(gaddr), "f"(v.x), "f"(v.y), "f"(v.z), "f"(v.w)
                 : "memory");

    if (q == 0) {
        atomicAdd(&g_cnt[tgt], 1.0f);
    }
}

// ---------------------------------------------------------------------------
// Kernel 3: m = msg/max(cnt,1); u = relu(X@Wu_x^T + m@Wu_m^T + b_upd);
//           y = u + x; out = LayerNorm(y) * gamma + beta.
// 256 threads/block, 8 nodes/block, 32 threads per node (2 outputs/lane),
// W_upd in shared (stride-129), LN via warp shfl reduction.
// ---------------------------------------------------------------------------
__global__ void update_kernel(const float* __restrict__ x,
                              const float* __restrict__ W_upd,
                              const float* __restrict__ b_upd,
                              const float* __restrict__ gamma,
                              const float* __restrict__ beta,
                              float* __restrict__ out) {
    __shared__ float Ws[64 * 129];
    __shared__ float xs[8][64];
    __shared__ float ms[8][64];
    const int tid = threadIdx.x;

    for (int i = tid; i < 64 * 128; i += 256) {
        Ws[(i >> 7) * 129 + (i & 127)] = W_upd[i];
    }

    const int group = tid >> 5;
    const int lane = tid & 31;
    const int node = blockIdx.x * 8 + group;

    const float inv = 1.0f / fmaxf(g_cnt[node], 1.0f);
    xs[group][lane]      = x[node * 64 + lane];
    xs[group][lane + 32] = x[node * 64 + lane + 32];
    ms[group][lane]      = g_msg[node * 64 + lane] * inv;
    ms[group][lane + 32] = g_msg[node * 64 + lane + 32] * inv;
    __syncthreads();

    float y[2];
    #pragma unroll
    for (int t = 0; t < 2; ++t) {
        const int j = lane + t * 32;
        float acc = __ldg(&b_upd[j]);
        const float* wr = &Ws[j * 129];
        #pragma unroll
        for (int k = 0; k < 64; ++k) acc += xs[group][k] * wr[k];
        #pragma unroll
        for (int k = 0; k < 64; ++k) acc += ms[group][k] * wr[64 + k];
        acc = fmaxf(acc, 0.0f);
        y[t] = acc + xs[group][j];
    }

    // LayerNorm over 64 values held 2-per-lane in this warp.
    float s = y[0] + y[1];
    float s2 = y[0] * y[0] + y[1] * y[1];
    #pragma unroll
    for (int o = 16; o > 0; o >>= 1) {
        s  += __shfl_xor_sync(0xFFFFFFFFu, s, o);
        s2 += __shfl_xor_sync(0xFFFFFFFFu, s2, o);
    }
    const float mu = s * (1.0f / 64.0f);
    const float var = s2 * (1.0f / 64.0f) - mu * mu;
    const float r = rsqrtf(var + 1e-5f);

    #pragma unroll
    for (int t = 0; t < 2; ++t) {
        const int j = lane + t * 32;
        out[node * 64 + j] = (y[t] - mu) * r * __ldg(&gamma[j]) + __ldg(&beta[j]);
    }
}

// ---------------------------------------------------------------------------
// Inputs (metadata order): node_features f32[N,64], edge_index i32[E,2],
// W_msg f32[64,128], b_msg f32[64], W_upd f32[64,128], b_upd f32[64],
// gamma f32[64], beta f32[64]. Output f32[N,64].
// ---------------------------------------------------------------------------
extern "C" void kernel_launch(void* const* d_in, const int* in_sizes, int n_in,
                              void* d_out, int out_size) {
    const float* x          = (const float*)d_in[0];
    const int* ei           = (const int*)d_in[1];
    const float* W_msg      = (const float*)d_in[2];
    const float* b_msg      = (const float*)d_in[3];
    const float* W_upd      = (const float*)d_in[4];
    const float* b_upd      = (const float*)d_in[5];
    const float* gamma      = (const float*)d_in[6];
    const float* beta       = (const float*)d_in[7];
    float* out              = (float*)d_out;

    precompute_kernel<<<NN / 8, 256>>>(x, W_msg, b_msg);           // 12500 blocks
    edge_kernel<<<(EE * 16) / 256, 256>>>(ei);                     // 100000 blocks
    update_kernel<<<NN / 8, 256>>>(x, W_upd, b_upd, gamma, beta, out);
}